// round 14
// baseline (speedup 1.0000x reference)
#include <cuda_runtime.h>
#include <cuda_bf16.h>
#include <math.h>
#include <stdint.h>

// ---------------- problem constants ----------------
#define BB      4
#define TT      4096
#define DIMV    1024
#define MFEAT   512
#define RROWS   (BB * TT)        // 16384 rows per tensor
#define NROWS   (2 * RROWS)      // 32768 X rows (Q then masked-K)
#define RSQRTM  0.04419417382415922f
#define EPSV    1e-8f

// int8 quantization scales (fixed; guarded on device)
#define SX      0.06f
#define INV_SX  16.666666f
#define XLIM    7.6f
#define SW      0.04f
#define INV_SW  25.0f
#define WLIM    5.0f
#define INV_SXSW 416.66667f      // 1/(SX*SW)

// ---------------- device scratch (static, allocation-free) ----------------
__device__ float g_qp[RROWS * MFEAT];       // fallback only (32 MB)
__device__ float g_kp[RROWS * MFEAT];       // fallback only (32 MB)
__device__ float g_xd[NROWS];
__device__ float g_ksum[BB * MFEAT];
__device__ float g_D[BB * TT];
__device__ float g_kptv[BB * DIMV * MFEAT]; // 8 MB
__device__ int   g_flag;                    // 1 => certificate failed -> exact path
                                            // (zero-init; reset at end of fallback)
__device__ float g_wnorm[MFEAT];            // per-row ||w_m||^2
__device__ unsigned char g_wq8[MFEAT * DIMV];         // w as s8 (512 KB)
__device__ unsigned char g_xq8[(size_t)NROWS * DIMV]; // X as s8 (32 MB)
__device__ unsigned g_bar_count;            // software grid barrier (fallback only)
__device__ unsigned g_bar_sense;

// ---------------- PTX helpers (sm_100-safe) ----------------
__device__ __forceinline__ uint32_t smem_u32(const void* p) {
    return (uint32_t)__cvta_generic_to_shared(p);
}
__device__ __forceinline__ void ldmx4(uint32_t* r, uint32_t addr) {
    asm volatile("ldmatrix.sync.aligned.m8n8.x4.shared.b16 {%0,%1,%2,%3}, [%4];"
                 : "=r"(r[0]), "=r"(r[1]), "=r"(r[2]), "=r"(r[3]) : "r"(addr));
}
__device__ __forceinline__ void mma_s8(int* c, const uint32_t* a, uint32_t b0, uint32_t b1) {
    asm volatile(
        "mma.sync.aligned.m16n8k32.row.col.s32.s8.s8.s32 "
        "{%0,%1,%2,%3},{%4,%5,%6,%7},{%8,%9},{%0,%1,%2,%3};"
        : "+r"(c[0]), "+r"(c[1]), "+r"(c[2]), "+r"(c[3])
        : "r"(a[0]), "r"(a[1]), "r"(a[2]), "r"(a[3]), "r"(b0), "r"(b1));
}
__device__ __forceinline__ void cp16(uint32_t dst, const void* src) {
    asm volatile("cp.async.cg.shared.global [%0], [%1], 16;" :: "r"(dst), "l"(src) : "memory");
}
#define CP_COMMIT() asm volatile("cp.async.commit_group;" ::: "memory")
#define CP_WAIT3()  asm volatile("cp.async.wait_group 3;" ::: "memory")

// quantize 4 floats -> 4 s8 bytes; sets *bad if any |v| exceeds lim (NaN-safe)
__device__ __forceinline__ uint32_t quant4(float4 v, float invs, float lim, bool* bad) {
    if (!(fabsf(v.x) <= lim) || !(fabsf(v.y) <= lim) ||
        !(fabsf(v.z) <= lim) || !(fabsf(v.w) <= lim)) *bad = true;
    int a = __float2int_rn(v.x * invs);
    int b = __float2int_rn(v.y * invs);
    int c = __float2int_rn(v.z * invs);
    int d = __float2int_rn(v.w * invs);
    return (uint32_t)(a & 255) | ((uint32_t)(b & 255) << 8)
         | ((uint32_t)(c & 255) << 16) | ((uint32_t)(d & 255) << 24);
}

// 64B-per-row tile swizzle: chunk = 16B unit (0..3)
__device__ __forceinline__ int swz(int r, int chunk) {
    return r * 64 + ((chunk ^ ((r >> 1) & 3)) << 4);
}

// ---------------- kernel 1: merged prep (w blocks + X blocks) ---------------
// blocks [0,64):    w -> s8 + per-row norms + |w| guard
// blocks [64,4160): X -> s8, fused xd + |x| guard
__global__ void __launch_bounds__(256)
prep_all(const float* __restrict__ Q, const float* __restrict__ Kin,
         const float* __restrict__ mask, const float* __restrict__ w) {
    const int warp = threadIdx.x >> 5;
    const int lane = threadIdx.x & 31;
    bool bad = false;

    if (blockIdx.x < 64) {
        int m = blockIdx.x * 8 + warp;          // 0..511
        const float4* p4 = reinterpret_cast<const float4*>(w + (size_t)m * DIMV);
        uint32_t* o4 = reinterpret_cast<uint32_t*>(g_wq8 + (size_t)m * DIMV);
        float s = 0.0f;
        #pragma unroll
        for (int j = 0; j < 8; j++) {
            float4 v = p4[lane + 32 * j];
            s += v.x * v.x + v.y * v.y + v.z * v.z + v.w * v.w;
            o4[lane + 32 * j] = quant4(v, INV_SW, WLIM, &bad);
        }
        #pragma unroll
        for (int o = 16; o; o >>= 1) s += __shfl_xor_sync(0xFFFFFFFFu, s, o);
        if (lane == 0) g_wnorm[m] = s;
        if (__any_sync(0xFFFFFFFFu, bad) && lane == 0) atomicOr(&g_flag, 1);
        return;
    }

    int grow = (blockIdx.x - 64) * 8 + warp;    // 0..NROWS-1
    const float* src;
    float ms;
    if (grow < RROWS) { src = Q + (size_t)grow * DIMV; ms = 1.0f; }
    else { int kr = grow - RROWS; src = Kin + (size_t)kr * DIMV; ms = mask[kr]; }

    const float4* s4 = reinterpret_cast<const float4*>(src);
    uint32_t* o4 = reinterpret_cast<uint32_t*>(g_xq8 + (size_t)grow * DIMV);
    float s = 0.0f;
    #pragma unroll
    for (int j = 0; j < 8; j++) {
        float4 v = s4[lane + 32 * j];
        v.x *= ms; v.y *= ms; v.z *= ms; v.w *= ms;
        s += v.x * v.x + v.y * v.y + v.z * v.z + v.w * v.w;
        o4[lane + 32 * j] = quant4(v, INV_SX, XLIM, &bad);
    }
    #pragma unroll
    for (int o = 16; o; o >>= 1) s += __shfl_xor_sync(0xFFFFFFFFu, s, o);
    if (lane == 0) g_xd[grow] = 0.5f * s;
    if (__any_sync(0xFFFFFFFFu, bad) && lane == 0) atomicOr(&g_flag, 1);
}

// ---------------- kernel 2: int8 certificate GEMM (+ output zeroing) --------
// Block 128(M) x 256(N), K stage 64 s8, 5-stage cp.async pipeline (wait 3).
// 512 threads = 16 warps as 4(M) x 4(N): warp tile 32x64 (inner loop identical
// to the proven 256-thread version). 25% less L2 traffic than 128x128 tiles.
#define CT_STAGES 5
#define CT_A_BYTES 8192                 // 128 x 64
#define CT_B_BYTES 16384                // 256 x 64
#define CT_STAGE_BYTES (CT_A_BYTES + CT_B_BYTES)   // 24 KB
#define CT_DYN (CT_STAGES * CT_STAGE_BYTES)        // 120 KB

extern __shared__ __align__(128) unsigned char ct_sm[];

__global__ void __launch_bounds__(512, 1)
cert_gemm(float* __restrict__ outz) {
    const int tid  = threadIdx.x;
    const int lane = tid & 31;
    const int warp = tid >> 5;           // 0..15
    const int wm = warp >> 2;            // 0..3 -> 32 M-rows
    const int wn = warp & 3;             // 0..3 -> 64 N-cols
    const int blockRow = blockIdx.y * 128;
    const int bn = blockIdx.x * 256;

    const uint32_t smb = smem_u32(ct_sm);

    // loaders: A 1x16B per thread (128 rows x 4 chunks = 512), B 2x16B per thread
    const int lrow = tid >> 2;           // 0..127
    const int lchunk = tid & 3;
    const int offA = swz(lrow, lchunk);
    int offB[2];
    const unsigned char* srcA = g_xq8 + (size_t)(blockRow + lrow) * DIMV + lchunk * 16;
    const unsigned char* srcB[2];
    #pragma unroll
    for (int h = 0; h < 2; h++) {
        int r = lrow + h * 128;
        offB[h] = swz(r, lchunk);
        srcB[h] = g_wq8 + (size_t)(bn + r) * DIMV + lchunk * 16;
    }

    int lA[2][2], lB[4][2];
    #pragma unroll
    for (int kh = 0; kh < 2; kh++) {
        #pragma unroll
        for (int mi = 0; mi < 2; mi++)
            lA[mi][kh] = swz(wm * 32 + mi * 16 + (lane & 15), kh * 2 + (lane >> 4));
        #pragma unroll
        for (int i = 0; i < 4; i++)
            lB[i][kh] = swz(wn * 64 + i * 16 + (lane & 7) + ((lane >> 4) << 3),
                            kh * 2 + ((lane >> 3) & 1));
    }

    int acc[2][8][4];
    #pragma unroll
    for (int mi = 0; mi < 2; mi++)
        #pragma unroll
        for (int nj = 0; nj < 8; nj++)
            #pragma unroll
            for (int e = 0; e < 4; e++) acc[mi][nj][e] = 0;

    // prologue: stages 0..3
    #pragma unroll
    for (int kt = 0; kt < 4; kt++) {
        uint32_t ab = smb + kt * CT_STAGE_BYTES;
        uint32_t bb = ab + CT_A_BYTES;
        cp16(ab + offA, srcA + kt * 64);
        #pragma unroll
        for (int h = 0; h < 2; h++)
            cp16(bb + offB[h], srcB[h] + kt * 64);
        CP_COMMIT();
    }

    const int NKT = DIMV / 64;           // 16 k-tiles
    int buf = 0, nbuf = 4;
    for (int kt = 0; kt < NKT; kt++) {
        CP_WAIT3();
        __syncthreads();                 // single sync per tile (stage reuse is
                                         // protected by next iteration's sync)
        if (kt + 4 < NKT) {
            uint32_t ab = smb + nbuf * CT_STAGE_BYTES;
            uint32_t bb = ab + CT_A_BYTES;
            cp16(ab + offA, srcA + (kt + 4) * 64);
            #pragma unroll
            for (int h = 0; h < 2; h++)
                cp16(bb + offB[h], srcB[h] + (kt + 4) * 64);
        }
        CP_COMMIT();

        uint32_t ab = smb + buf * CT_STAGE_BYTES;
        uint32_t bb = ab + CT_A_BYTES;
        #pragma unroll
        for (int kh = 0; kh < 2; kh++) {
            uint32_t a0[4], a1[4], b[4][4];
            ldmx4(a0, ab + lA[0][kh]);
            ldmx4(a1, ab + lA[1][kh]);
            #pragma unroll
            for (int i = 0; i < 4; i++) ldmx4(b[i], bb + lB[i][kh]);
            #pragma unroll
            for (int i = 0; i < 4; i++) {
                mma_s8(acc[0][2 * i],     a0, b[i][0], b[i][1]);
                mma_s8(acc[0][2 * i + 1], a0, b[i][2], b[i][3]);
                mma_s8(acc[1][2 * i],     a1, b[i][0], b[i][1]);
                mma_s8(acc[1][2 * i + 1], a1, b[i][2], b[i][3]);
            }
        }
        buf  = (buf == CT_STAGES - 1) ? 0 : buf + 1;
        nbuf = (nbuf == CT_STAGES - 1) ? 0 : nbuf + 1;
    }

    // zero this CTA's 128KB slice of the output (DRAM idle here; overlaps waves)
    {
        float4* oz = reinterpret_cast<float4*>(outz)
                   + ((size_t)blockIdx.y * gridDim.x + blockIdx.x) * 8192;
        #pragma unroll
        for (int j = 0; j < 16; j++)
            oz[tid + 512 * j] = make_float4(0.f, 0.f, 0.f, 0.f);
    }

    // ---- epilogue: rigor guards + per-row int8 threshold ----
    // exact wtx <= SX*SW*acc + 34 + 0.906*sqrt(xd) + 1  (given |x|<=7.6, |w|<=5,
    // ||w_m||^2<=1250; int32 accumulation exact). Feature exactly 0 iff
    // wtx - xd <= -104; require SX*SW*acc <= xd - 148 - 0.906*sqrt(xd).
    bool bad = false;
    if (!(g_wnorm[tid] <= 1250.0f)) bad = true;   // 512 threads x 1 entry
    #pragma unroll
    for (int mi = 0; mi < 2; mi++) {
        int r0 = blockRow + wm * 32 + mi * 16 + (lane >> 2);
        float xd0 = g_xd[r0];
        float xd1 = g_xd[r0 + 8];
        if (!(xd0 <= 7000.0f) || !(xd1 <= 7000.0f)) bad = true;   // catches NaN
        float t0 = (xd0 - 148.0f - 0.906f * sqrtf(fmaxf(xd0, 0.0f))) * INV_SXSW;
        float t1 = (xd1 - 148.0f - 0.906f * sqrtf(fmaxf(xd1, 0.0f))) * INV_SXSW;
        #pragma unroll
        for (int nj = 0; nj < 8; nj++) {
            if (!((float)acc[mi][nj][0] <= t0)) bad = true;
            if (!((float)acc[mi][nj][1] <= t0)) bad = true;
            if (!((float)acc[mi][nj][2] <= t1)) bad = true;
            if (!((float)acc[mi][nj][3] <= t1)) bad = true;
        }
    }
    if (__syncthreads_or(bad ? 1 : 0)) {
        if (tid == 0) atomicOr(&g_flag, 1);
    }
}

// ========== single persistent gated fallback (exact fp32; runs iff g_flag) ==
#define FB_GRID 132
#define BMt 128
#define BNt 64
#define BKt 16
#define FEAT_TILES ((MFEAT / BNt) * (NROWS / BMt))     // 2048
#define KPTV_TILES ((MFEAT / 16) * (DIMV / 16) * BB)   // 8192
#define YF_TILES   ((DIMV / 16) * (TT / 16) * BB)      // 65536

__device__ __forceinline__ void grid_bar() {
    __syncthreads();
    if (threadIdx.x == 0) {
        __threadfence();
        unsigned s0 = atomicAdd(&g_bar_sense, 0u);
        unsigned old = atomicAdd(&g_bar_count, 1u);
        if (old == (unsigned)gridDim.x - 1u) {
            g_bar_count = 0u;
            __threadfence();
            atomicExch(&g_bar_sense, s0 + 1u);
        } else {
            while (atomicAdd(&g_bar_sense, 0u) == s0) {}
        }
    }
    __syncthreads();
}

__global__ void __launch_bounds__(256)
fallback_kernel(const float* __restrict__ Q, const float* __restrict__ Kin,
                const float* __restrict__ V, const float* __restrict__ mask,
                const float* __restrict__ w, float* __restrict__ out) {
    if (g_flag == 0) return;

    __shared__ float As[2][BKt][BMt];
    __shared__ float Bs[2][BKt][BNt];
    __shared__ float T0[16][17], T1[16][17];
    __shared__ float ws[8];

    const int tid = threadIdx.x;
    const int tx16 = tid & 15;
    const int ty16 = tid >> 4;

    // ---------- phase A: feature GEMM + exp -> g_qp / g_kp ----------
    {
        const int tx = tid & 15;
        const int ty = tid >> 4;
        const int lrow = tid >> 2;
        const int lk   = (tid & 3) * 4;
        const int qsw  = (tid & 3);
        for (int tile = blockIdx.x; tile < FEAT_TILES; tile += gridDim.x) {
            const int bm = (tile >> 3) * BMt;
            const int bn = (tile & 7) * BNt;

            const float* aptr[2];
            float ascale[2];
            #pragma unroll
            for (int i = 0; i < 2; i++) {
                int gr = bm + lrow + 64 * i;
                if (gr < RROWS) { aptr[i] = Q + (size_t)gr * DIMV; ascale[i] = 1.0f; }
                else { int kr = gr - RROWS; aptr[i] = Kin + (size_t)kr * DIMV; ascale[i] = mask[kr]; }
            }
            const float* bptr = w + (size_t)(bn + lrow) * DIMV;

            float4 aReg[2], bReg;
            float acc[8][4];
            #pragma unroll
            for (int i = 0; i < 8; i++)
                #pragma unroll
                for (int j = 0; j < 4; j++) acc[i][j] = 0.0f;

            #pragma unroll
            for (int i = 0; i < 2; i++) {
                float4 v = *reinterpret_cast<const float4*>(aptr[i] + lk);
                v.x *= ascale[i]; v.y *= ascale[i]; v.z *= ascale[i]; v.w *= ascale[i];
                aReg[i] = v;
            }
            bReg = *reinterpret_cast<const float4*>(bptr + lk);
            {
                #pragma unroll
                for (int i = 0; i < 2; i++) {
                    int row = lrow + 64 * i;
                    int col = row ^ (qsw * 8);
                    As[0][lk + 0][col] = aReg[i].x;
                    As[0][lk + 1][col] = aReg[i].y;
                    As[0][lk + 2][col] = aReg[i].z;
                    As[0][lk + 3][col] = aReg[i].w;
                }
                int col = lrow ^ (qsw * 8);
                Bs[0][lk + 0][col] = bReg.x;
                Bs[0][lk + 1][col] = bReg.y;
                Bs[0][lk + 2][col] = bReg.z;
                Bs[0][lk + 3][col] = bReg.w;
            }
            __syncthreads();

            int buf = 0;
            const int NKT = DIMV / BKt;
            for (int kt = 0; kt < NKT; kt++) {
                if (kt < NKT - 1) {
                    int k0 = (kt + 1) * BKt;
                    #pragma unroll
                    for (int i = 0; i < 2; i++) {
                        float4 v = *reinterpret_cast<const float4*>(aptr[i] + k0 + lk);
                        v.x *= ascale[i]; v.y *= ascale[i]; v.z *= ascale[i]; v.w *= ascale[i];
                        aReg[i] = v;
                    }
                    bReg = *reinterpret_cast<const float4*>(bptr + k0 + lk);
                }
                #pragma unroll
                for (int k = 0; k < BKt; k++) {
                    int qr = k >> 2;
                    int cA = (ty ^ qr) * 8;
                    float4 a0 = *reinterpret_cast<const float4*>(&As[buf][k][cA]);
                    float4 a1 = *reinterpret_cast<const float4*>(&As[buf][k][cA + 4]);
                    int cB = (tx * 4) ^ (qr * 8);
                    float4 b0 = *reinterpret_cast<const float4*>(&Bs[buf][k][cB]);
                    float av[8] = {a0.x, a0.y, a0.z, a0.w, a1.x, a1.y, a1.z, a1.w};
                    float bv[4] = {b0.x, b0.y, b0.z, b0.w};
                    #pragma unroll
                    for (int i = 0; i < 8; i++)
                        #pragma unroll
                        for (int j = 0; j < 4; j++)
                            acc[i][j] = fmaf(av[i], bv[j], acc[i][j]);
                }
                if (kt < NKT - 1) {
                    int nb = buf ^ 1;
                    #pragma unroll
                    for (int i = 0; i < 2; i++) {
                        int row = lrow + 64 * i;
                        int col = row ^ (qsw * 8);
                        As[nb][lk + 0][col] = aReg[i].x;
                        As[nb][lk + 1][col] = aReg[i].y;
                        As[nb][lk + 2][col] = aReg[i].z;
                        As[nb][lk + 3][col] = aReg[i].w;
                    }
                    int col = lrow ^ (qsw * 8);
                    Bs[nb][lk + 0][col] = bReg.x;
                    Bs[nb][lk + 1][col] = bReg.y;
                    Bs[nb][lk + 2][col] = bReg.z;
                    Bs[nb][lk + 3][col] = bReg.w;
                    __syncthreads();
                    buf = nb;
                }
            }
            #pragma unroll
            for (int i = 0; i < 8; i++) {
                int r = bm + ty * 8 + i;
                float xd = g_xd[r];
                float4 o;
                o.x = expf(acc[i][0] - xd) * RSQRTM;
                o.y = expf(acc[i][1] - xd) * RSQRTM;
                o.z = expf(acc[i][2] - xd) * RSQRTM;
                o.w = expf(acc[i][3] - xd) * RSQRTM;
                float* outp = (r < RROWS) ? (g_qp + (size_t)r * MFEAT)
                                          : (g_kp + (size_t)(r - RROWS) * MFEAT);
                *reinterpret_cast<float4*>(outp + bn + tx * 4) = o;
            }
            __syncthreads();
        }
    }
    grid_bar();

    // ---------- phase B: ksum ----------
    for (int idx = blockIdx.x * 256 + tid; idx < BB * MFEAT; idx += gridDim.x * 256) {
        int b = idx / MFEAT, m = idx % MFEAT;
        float acc = 0.0f;
        for (int t = 0; t < TT; t++)
            acc += g_kp[((size_t)b * TT + t) * MFEAT + m];
        g_ksum[idx] = acc;
    }
    grid_bar();

    // ---------- phase C: D ----------
    for (int bt = blockIdx.x; bt < BB * TT; bt += gridDim.x) {
        int b = bt / TT;
        float acc = 0.0f;
        #pragma unroll
        for (int m = tid; m < MFEAT; m += 256)
            acc += g_qp[(size_t)bt * MFEAT + m] * g_ksum[b * MFEAT + m];
        #pragma unroll
        for (int o = 16; o; o >>= 1) acc += __shfl_xor_sync(0xFFFFFFFFu, acc, o);
        if ((tid & 31) == 0) ws[tid >> 5] = acc;
        __syncthreads();
        if (tid == 0) {
            float s = 0.0f;
            #pragma unroll
            for (int i = 0; i < 8; i++) s += ws[i];
            g_D[bt] = s;
        }
        __syncthreads();
    }

    // ---------- phase D: kptv ----------
    for (int tile = blockIdx.x; tile < KPTV_TILES; tile += gridDim.x) {
        int b = tile / ((MFEAT / 16) * (DIMV / 16));
        int rem = tile % ((MFEAT / 16) * (DIMV / 16));
        int n0 = (rem / (MFEAT / 16)) * 16;
        int m0 = (rem % (MFEAT / 16)) * 16;
        float acc = 0.0f;
        for (int t0 = 0; t0 < TT; t0 += 16) {
            int t = t0 + ty16;
            T0[ty16][tx16] = V[((size_t)b * TT + t) * DIMV + n0 + tx16] * mask[b * TT + t];
            T1[ty16][tx16] = g_kp[((size_t)b * TT + t) * MFEAT + m0 + tx16];
            __syncthreads();
            #pragma unroll
            for (int kk = 0; kk < 16; kk++)
                acc = fmaf(T0[kk][ty16], T1[kk][tx16], acc);
            __syncthreads();
        }
        g_kptv[((size_t)b * DIMV + n0 + ty16) * MFEAT + m0 + tx16] = acc;
        __syncthreads();
    }
    grid_bar();

    // ---------- phase E: y ----------
    for (int tile = blockIdx.x; tile < YF_TILES; tile += gridDim.x) {
        int b = tile / ((DIMV / 16) * (TT / 16));
        int rem = tile % ((DIMV / 16) * (TT / 16));
        int t0 = (rem / (DIMV / 16)) * 16;
        int n0 = (rem % (DIMV / 16)) * 16;
        float acc = 0.0f;
        for (int m0 = 0; m0 < MFEAT; m0 += 16) {
            T0[ty16][tx16] = g_qp[((size_t)b * TT + t0 + ty16) * MFEAT + m0 + tx16];
            T1[ty16][tx16] = g_kptv[((size_t)b * DIMV + n0 + ty16) * MFEAT + m0 + tx16];
            __syncthreads();
            #pragma unroll
            for (int kk = 0; kk < 16; kk++)
                acc = fmaf(T0[ty16][kk], T1[tx16][kk], acc);
            __syncthreads();
        }
        int t = t0 + ty16;
        float inv = 1.0f / (g_D[b * TT + t] + EPSV);
        out[((size_t)b * TT + t) * DIMV + n0 + tx16] = acc * inv * inv;
        __syncthreads();
    }

    // reset flag for the next graph replay (all blocks done with flag-dependent work)
    grid_bar();
    if (blockIdx.x == 0 && tid == 0) g_flag = 0;
}

// ---------------- launch ----------------
extern "C" void kernel_launch(void* const* d_in, const int* in_sizes, int n_in,
                              void* d_out, int out_size) {
    const float* Q    = (const float*)d_in[0];
    const float* K    = (const float*)d_in[1];
    const float* V    = (const float*)d_in[2];
    const float* mask = (const float*)d_in[3];
    const float* w    = (const float*)d_in[4];
    float* out = (float*)d_out;
    (void)in_sizes; (void)n_in; (void)out_size;

    cudaFuncSetAttribute(cert_gemm, cudaFuncAttributeMaxDynamicSharedMemorySize, CT_DYN);

    prep_all<<<64 + NROWS / 8, 256>>>(Q, K, mask, w);
    cert_gemm<<<dim3(MFEAT / 256, NROWS / 128), 512, CT_DYN>>>(out);
    fallback_kernel<<<FB_GRID, 256>>>(Q, K, V, mask, w, out);
}

// round 16
// speedup vs baseline: 1.1380x; 1.1380x over previous
#include <cuda_runtime.h>
#include <cuda_bf16.h>
#include <math.h>
#include <stdint.h>

// ---------------- problem constants ----------------
#define BB      4
#define TT      4096
#define DIMV    1024
#define MFEAT   512
#define RROWS   (BB * TT)        // 16384 rows per tensor
#define NROWS   (2 * RROWS)      // 32768 X rows (Q then masked-K)
#define RSQRTM  0.04419417382415922f
#define EPSV    1e-8f

// int8 quantization scales (fixed; guarded on device)
#define SX      0.06f
#define INV_SX  16.666666f
#define XLIM    7.6f
#define SW      0.04f
#define INV_SW  25.0f
#define WLIM    5.0f
#define INV_SXSW 416.66667f      // 1/(SX*SW)

// ---------------- device scratch (static, allocation-free) ----------------
__device__ float g_qp[RROWS * MFEAT];       // fallback only (32 MB)
__device__ float g_kp[RROWS * MFEAT];       // fallback only (32 MB)
__device__ float g_xd[NROWS];
__device__ float g_ksum[BB * MFEAT];
__device__ float g_D[BB * TT];
__device__ float g_kptv[BB * DIMV * MFEAT]; // 8 MB
__device__ int   g_flag;                    // 1 => certificate failed -> exact path
                                            // (zero-init; reset at end of fallback)
__device__ float g_wnorm[MFEAT];            // per-row ||w_m||^2
__device__ unsigned char g_wq8[MFEAT * DIMV];         // w as s8 (512 KB)
__device__ unsigned char g_xq8[(size_t)NROWS * DIMV]; // X as s8 (32 MB)
__device__ unsigned g_bar_count;            // software grid barrier (fallback only)
__device__ unsigned g_bar_sense;

// ---------------- PTX helpers (sm_100-safe) ----------------
__device__ __forceinline__ uint32_t smem_u32(const void* p) {
    return (uint32_t)__cvta_generic_to_shared(p);
}
__device__ __forceinline__ void ldmx4(uint32_t* r, uint32_t addr) {
    asm volatile("ldmatrix.sync.aligned.m8n8.x4.shared.b16 {%0,%1,%2,%3}, [%4];"
                 : "=r"(r[0]), "=r"(r[1]), "=r"(r[2]), "=r"(r[3]) : "r"(addr));
}
__device__ __forceinline__ void mma_s8(int* c, const uint32_t* a, uint32_t b0, uint32_t b1) {
    asm volatile(
        "mma.sync.aligned.m16n8k32.row.col.s32.s8.s8.s32 "
        "{%0,%1,%2,%3},{%4,%5,%6,%7},{%8,%9},{%0,%1,%2,%3};"
        : "+r"(c[0]), "+r"(c[1]), "+r"(c[2]), "+r"(c[3])
        : "r"(a[0]), "r"(a[1]), "r"(a[2]), "r"(a[3]), "r"(b0), "r"(b1));
}
__device__ __forceinline__ void cp16(uint32_t dst, const void* src) {
    asm volatile("cp.async.cg.shared.global [%0], [%1], 16;" :: "r"(dst), "l"(src) : "memory");
}
#define CP_COMMIT() asm volatile("cp.async.commit_group;" ::: "memory")
#define CP_WAIT4()  asm volatile("cp.async.wait_group 4;" ::: "memory")

// quantize 4 floats -> 4 s8 bytes; sets *bad if any |v| exceeds lim (NaN-safe)
__device__ __forceinline__ uint32_t quant4(float4 v, float invs, float lim, bool* bad) {
    if (!(fabsf(v.x) <= lim) || !(fabsf(v.y) <= lim) ||
        !(fabsf(v.z) <= lim) || !(fabsf(v.w) <= lim)) *bad = true;
    int a = __float2int_rn(v.x * invs);
    int b = __float2int_rn(v.y * invs);
    int c = __float2int_rn(v.z * invs);
    int d = __float2int_rn(v.w * invs);
    return (uint32_t)(a & 255) | ((uint32_t)(b & 255) << 8)
         | ((uint32_t)(c & 255) << 16) | ((uint32_t)(d & 255) << 24);
}

// 64B-per-row tile swizzle: chunk = 16B unit (0..3)
__device__ __forceinline__ int swz(int r, int chunk) {
    return r * 64 + ((chunk ^ ((r >> 1) & 3)) << 4);
}

// ---------------- kernel 1: merged prep (w blocks + X blocks) ---------------
// blocks [0,64):    w -> s8 + per-row norms + |w| guard
// blocks [64,4160): X -> s8, fused xd + |x| guard
__global__ void __launch_bounds__(256)
prep_all(const float* __restrict__ Q, const float* __restrict__ Kin,
         const float* __restrict__ mask, const float* __restrict__ w) {
    const int warp = threadIdx.x >> 5;
    const int lane = threadIdx.x & 31;
    bool bad = false;

    if (blockIdx.x < 64) {
        int m = blockIdx.x * 8 + warp;          // 0..511
        const float4* p4 = reinterpret_cast<const float4*>(w + (size_t)m * DIMV);
        uint32_t* o4 = reinterpret_cast<uint32_t*>(g_wq8 + (size_t)m * DIMV);
        float s = 0.0f;
        #pragma unroll
        for (int j = 0; j < 8; j++) {
            float4 v = p4[lane + 32 * j];
            s += v.x * v.x + v.y * v.y + v.z * v.z + v.w * v.w;
            o4[lane + 32 * j] = quant4(v, INV_SW, WLIM, &bad);
        }
        #pragma unroll
        for (int o = 16; o; o >>= 1) s += __shfl_xor_sync(0xFFFFFFFFu, s, o);
        if (lane == 0) g_wnorm[m] = s;
        if (__any_sync(0xFFFFFFFFu, bad) && lane == 0) atomicOr(&g_flag, 1);
        return;
    }

    int grow = (blockIdx.x - 64) * 8 + warp;    // 0..NROWS-1
    const float* src;
    float ms;
    if (grow < RROWS) { src = Q + (size_t)grow * DIMV; ms = 1.0f; }
    else { int kr = grow - RROWS; src = Kin + (size_t)kr * DIMV; ms = mask[kr]; }

    const float4* s4 = reinterpret_cast<const float4*>(src);
    uint32_t* o4 = reinterpret_cast<uint32_t*>(g_xq8 + (size_t)grow * DIMV);
    float s = 0.0f;
    #pragma unroll
    for (int j = 0; j < 8; j++) {
        float4 v = s4[lane + 32 * j];
        v.x *= ms; v.y *= ms; v.z *= ms; v.w *= ms;
        s += v.x * v.x + v.y * v.y + v.z * v.z + v.w * v.w;
        o4[lane + 32 * j] = quant4(v, INV_SX, XLIM, &bad);
    }
    #pragma unroll
    for (int o = 16; o; o >>= 1) s += __shfl_xor_sync(0xFFFFFFFFu, s, o);
    if (lane == 0) g_xd[grow] = 0.5f * s;
    if (__any_sync(0xFFFFFFFFu, bad) && lane == 0) atomicOr(&g_flag, 1);
}

// ---------------- kernel 2: int8 certificate GEMM (+ output zeroing) --------
// Block 128(M) x 128(N), K stage 64 s8, 6-stage cp.async pipeline (wait 4).
// 8 warps 4x2, warp tile 32x64. Exact int32 accumulation; per-row threshold.
#define CT_STAGES 6
#define CT_STAGE_BYTES 16384            // A 8KB + B 8KB
#define CT_DYN (CT_STAGES * CT_STAGE_BYTES)     // 96 KB

extern __shared__ __align__(128) unsigned char ct_sm[];

__global__ void __launch_bounds__(256, 2)
cert_gemm(float* __restrict__ outz) {
    const int tid  = threadIdx.x;
    const int lane = tid & 31;
    const int warp = tid >> 5;
    const int wm = warp >> 1;
    const int wn = warp & 1;
    const int blockRow = blockIdx.y * 128;
    const int bn = blockIdx.x * 128;

    const uint32_t smb = smem_u32(ct_sm);

    const int lrow = tid >> 2;           // 0..63
    const int lchunk = tid & 3;
    int offA[2];
    const unsigned char* srcA[2];
    const unsigned char* srcB[2];
    #pragma unroll
    for (int h = 0; h < 2; h++) {
        int r = lrow + h * 64;
        offA[h] = swz(r, lchunk);
        srcA[h] = g_xq8 + (size_t)(blockRow + r) * DIMV + lchunk * 16;
        srcB[h] = g_wq8 + (size_t)(bn + r) * DIMV + lchunk * 16;
    }

    int lA[2][2], lB[4][2];
    #pragma unroll
    for (int kh = 0; kh < 2; kh++) {
        #pragma unroll
        for (int mi = 0; mi < 2; mi++)
            lA[mi][kh] = swz(wm * 32 + mi * 16 + (lane & 15), kh * 2 + (lane >> 4));
        #pragma unroll
        for (int i = 0; i < 4; i++)
            lB[i][kh] = swz(wn * 64 + i * 16 + (lane & 7) + ((lane >> 4) << 3),
                            kh * 2 + ((lane >> 3) & 1));
    }

    int acc[2][8][4];
    #pragma unroll
    for (int mi = 0; mi < 2; mi++)
        #pragma unroll
        for (int nj = 0; nj < 8; nj++)
            #pragma unroll
            for (int e = 0; e < 4; e++) acc[mi][nj][e] = 0;

    // prologue: stages 0..4
    #pragma unroll
    for (int kt = 0; kt < 5; kt++) {
        uint32_t ab = smb + kt * CT_STAGE_BYTES;
        uint32_t bb = ab + 8192;
        #pragma unroll
        for (int h = 0; h < 2; h++) {
            cp16(ab + offA[h], srcA[h] + kt * 64);
            cp16(bb + offA[h], srcB[h] + kt * 64);
        }
        CP_COMMIT();
    }

    const int NKT = DIMV / 64;           // 16 k-tiles
    int buf = 0, nbuf = 5;
    for (int kt = 0; kt < NKT; kt++) {
        CP_WAIT4();
        __syncthreads();                 // single sync per tile: also protects
                                         // stage reuse (write of kt+6 happens
                                         // after next iteration's sync)
        if (kt + 5 < NKT) {
            uint32_t ab = smb + nbuf * CT_STAGE_BYTES;
            uint32_t bb = ab + 8192;
            #pragma unroll
            for (int h = 0; h < 2; h++) {
                cp16(ab + offA[h], srcA[h] + (kt + 5) * 64);
                cp16(bb + offA[h], srcB[h] + (kt + 5) * 64);
            }
        }
        CP_COMMIT();

        uint32_t ab = smb + buf * CT_STAGE_BYTES;
        uint32_t bb = ab + 8192;
        #pragma unroll
        for (int kh = 0; kh < 2; kh++) {
            uint32_t a0[4], a1[4], b[4][4];
            ldmx4(a0, ab + lA[0][kh]);
            ldmx4(a1, ab + lA[1][kh]);
            #pragma unroll
            for (int i = 0; i < 4; i++) ldmx4(b[i], bb + lB[i][kh]);
            #pragma unroll
            for (int i = 0; i < 4; i++) {
                mma_s8(acc[0][2 * i],     a0, b[i][0], b[i][1]);
                mma_s8(acc[0][2 * i + 1], a0, b[i][2], b[i][3]);
                mma_s8(acc[1][2 * i],     a1, b[i][0], b[i][1]);
                mma_s8(acc[1][2 * i + 1], a1, b[i][2], b[i][3]);
            }
        }
        buf  = (buf == CT_STAGES - 1) ? 0 : buf + 1;
        nbuf = (nbuf == CT_STAGES - 1) ? 0 : nbuf + 1;
    }

    // zero this CTA's 64KB slice of the output (DRAM idle here; overlaps waves)
    {
        float4* oz = reinterpret_cast<float4*>(outz)
                   + ((size_t)blockIdx.y * gridDim.x + blockIdx.x) * 4096;
        #pragma unroll
        for (int j = 0; j < 16; j++)
            oz[tid + 256 * j] = make_float4(0.f, 0.f, 0.f, 0.f);
    }

    // ---- epilogue: rigor guards + per-row int8 threshold ----
    // exact wtx <= SX*SW*acc + 34 + 0.906*sqrt(xd) + 1  (given |x|<=7.6, |w|<=5,
    // ||w_m||^2<=1250; int32 accumulation exact). Feature exactly 0 iff
    // wtx - xd <= -104; require SX*SW*acc <= xd - 148 - 0.906*sqrt(xd).
    bool bad = false;
    if (!(g_wnorm[tid] <= 1250.0f)) bad = true;
    if (!(g_wnorm[tid + 256] <= 1250.0f)) bad = true;
    #pragma unroll
    for (int mi = 0; mi < 2; mi++) {
        int r0 = blockRow + wm * 32 + mi * 16 + (lane >> 2);
        float xd0 = g_xd[r0];
        float xd1 = g_xd[r0 + 8];
        if (!(xd0 <= 7000.0f) || !(xd1 <= 7000.0f)) bad = true;   // catches NaN
        float t0 = (xd0 - 148.0f - 0.906f * sqrtf(fmaxf(xd0, 0.0f))) * INV_SXSW;
        float t1 = (xd1 - 148.0f - 0.906f * sqrtf(fmaxf(xd1, 0.0f))) * INV_SXSW;
        #pragma unroll
        for (int nj = 0; nj < 8; nj++) {
            if (!((float)acc[mi][nj][0] <= t0)) bad = true;
            if (!((float)acc[mi][nj][1] <= t0)) bad = true;
            if (!((float)acc[mi][nj][2] <= t1)) bad = true;
            if (!((float)acc[mi][nj][3] <= t1)) bad = true;
        }
    }
    if (__syncthreads_or(bad ? 1 : 0)) {
        if (tid == 0) atomicOr(&g_flag, 1);
    }
}

// ========== single persistent gated fallback (exact fp32; runs iff g_flag) ==
#define FB_GRID 132
#define BMt 128
#define BNt 64
#define BKt 16
#define FEAT_TILES ((MFEAT / BNt) * (NROWS / BMt))     // 2048
#define KPTV_TILES ((MFEAT / 16) * (DIMV / 16) * BB)   // 8192
#define YF_TILES   ((DIMV / 16) * (TT / 16) * BB)      // 65536

__device__ __forceinline__ void grid_bar() {
    __syncthreads();
    if (threadIdx.x == 0) {
        __threadfence();
        unsigned s0 = atomicAdd(&g_bar_sense, 0u);
        unsigned old = atomicAdd(&g_bar_count, 1u);
        if (old == (unsigned)gridDim.x - 1u) {
            g_bar_count = 0u;
            __threadfence();
            atomicExch(&g_bar_sense, s0 + 1u);
        } else {
            while (atomicAdd(&g_bar_sense, 0u) == s0) {}
        }
    }
    __syncthreads();
}

__global__ void __launch_bounds__(256)
fallback_kernel(const float* __restrict__ Q, const float* __restrict__ Kin,
                const float* __restrict__ V, const float* __restrict__ mask,
                const float* __restrict__ w, float* __restrict__ out) {
    if (g_flag == 0) return;

    __shared__ float As[2][BKt][BMt];
    __shared__ float Bs[2][BKt][BNt];
    __shared__ float T0[16][17], T1[16][17];
    __shared__ float ws[8];

    const int tid = threadIdx.x;
    const int tx16 = tid & 15;
    const int ty16 = tid >> 4;

    // ---------- phase A: feature GEMM + exp -> g_qp / g_kp ----------
    {
        const int tx = tid & 15;
        const int ty = tid >> 4;
        const int lrow = tid >> 2;
        const int lk   = (tid & 3) * 4;
        const int qsw  = (tid & 3);
        for (int tile = blockIdx.x; tile < FEAT_TILES; tile += gridDim.x) {
            const int bm = (tile >> 3) * BMt;
            const int bn = (tile & 7) * BNt;

            const float* aptr[2];
            float ascale[2];
            #pragma unroll
            for (int i = 0; i < 2; i++) {
                int gr = bm + lrow + 64 * i;
                if (gr < RROWS) { aptr[i] = Q + (size_t)gr * DIMV; ascale[i] = 1.0f; }
                else { int kr = gr - RROWS; aptr[i] = Kin + (size_t)kr * DIMV; ascale[i] = mask[kr]; }
            }
            const float* bptr = w + (size_t)(bn + lrow) * DIMV;

            float4 aReg[2], bReg;
            float acc[8][4];
            #pragma unroll
            for (int i = 0; i < 8; i++)
                #pragma unroll
                for (int j = 0; j < 4; j++) acc[i][j] = 0.0f;

            #pragma unroll
            for (int i = 0; i < 2; i++) {
                float4 v = *reinterpret_cast<const float4*>(aptr[i] + lk);
                v.x *= ascale[i]; v.y *= ascale[i]; v.z *= ascale[i]; v.w *= ascale[i];
                aReg[i] = v;
            }
            bReg = *reinterpret_cast<const float4*>(bptr + lk);
            {
                #pragma unroll
                for (int i = 0; i < 2; i++) {
                    int row = lrow + 64 * i;
                    int col = row ^ (qsw * 8);
                    As[0][lk + 0][col] = aReg[i].x;
                    As[0][lk + 1][col] = aReg[i].y;
                    As[0][lk + 2][col] = aReg[i].z;
                    As[0][lk + 3][col] = aReg[i].w;
                }
                int col = lrow ^ (qsw * 8);
                Bs[0][lk + 0][col] = bReg.x;
                Bs[0][lk + 1][col] = bReg.y;
                Bs[0][lk + 2][col] = bReg.z;
                Bs[0][lk + 3][col] = bReg.w;
            }
            __syncthreads();

            int buf = 0;
            const int NKT = DIMV / BKt;
            for (int kt = 0; kt < NKT; kt++) {
                if (kt < NKT - 1) {
                    int k0 = (kt + 1) * BKt;
                    #pragma unroll
                    for (int i = 0; i < 2; i++) {
                        float4 v = *reinterpret_cast<const float4*>(aptr[i] + k0 + lk);
                        v.x *= ascale[i]; v.y *= ascale[i]; v.z *= ascale[i]; v.w *= ascale[i];
                        aReg[i] = v;
                    }
                    bReg = *reinterpret_cast<const float4*>(bptr + k0 + lk);
                }
                #pragma unroll
                for (int k = 0; k < BKt; k++) {
                    int qr = k >> 2;
                    int cA = (ty ^ qr) * 8;
                    float4 a0 = *reinterpret_cast<const float4*>(&As[buf][k][cA]);
                    float4 a1 = *reinterpret_cast<const float4*>(&As[buf][k][cA + 4]);
                    int cB = (tx * 4) ^ (qr * 8);
                    float4 b0 = *reinterpret_cast<const float4*>(&Bs[buf][k][cB]);
                    float av[8] = {a0.x, a0.y, a0.z, a0.w, a1.x, a1.y, a1.z, a1.w};
                    float bv[4] = {b0.x, b0.y, b0.z, b0.w};
                    #pragma unroll
                    for (int i = 0; i < 8; i++)
                        #pragma unroll
                        for (int j = 0; j < 4; j++)
                            acc[i][j] = fmaf(av[i], bv[j], acc[i][j]);
                }
                if (kt < NKT - 1) {
                    int nb = buf ^ 1;
                    #pragma unroll
                    for (int i = 0; i < 2; i++) {
                        int row = lrow + 64 * i;
                        int col = row ^ (qsw * 8);
                        As[nb][lk + 0][col] = aReg[i].x;
                        As[nb][lk + 1][col] = aReg[i].y;
                        As[nb][lk + 2][col] = aReg[i].z;
                        As[nb][lk + 3][col] = aReg[i].w;
                    }
                    int col = lrow ^ (qsw * 8);
                    Bs[nb][lk + 0][col] = bReg.x;
                    Bs[nb][lk + 1][col] = bReg.y;
                    Bs[nb][lk + 2][col] = bReg.z;
                    Bs[nb][lk + 3][col] = bReg.w;
                    __syncthreads();
                    buf = nb;
                }
            }
            #pragma unroll
            for (int i = 0; i < 8; i++) {
                int r = bm + ty * 8 + i;
                float xd = g_xd[r];
                float4 o;
                o.x = expf(acc[i][0] - xd) * RSQRTM;
                o.y = expf(acc[i][1] - xd) * RSQRTM;
                o.z = expf(acc[i][2] - xd) * RSQRTM;
                o.w = expf(acc[i][3] - xd) * RSQRTM;
                float* outp = (r < RROWS) ? (g_qp + (size_t)r * MFEAT)
                                          : (g_kp + (size_t)(r - RROWS) * MFEAT);
                *reinterpret_cast<float4*>(outp + bn + tx * 4) = o;
            }
            __syncthreads();
        }
    }
    grid_bar();

    // ---------- phase B: ksum ----------
    for (int idx = blockIdx.x * 256 + tid; idx < BB * MFEAT; idx += gridDim.x * 256) {
        int b = idx / MFEAT, m = idx % MFEAT;
        float acc = 0.0f;
        for (int t = 0; t < TT; t++)
            acc += g_kp[((size_t)b * TT + t) * MFEAT + m];
        g_ksum[idx] = acc;
    }
    grid_bar();

    // ---------- phase C: D ----------
    for (int bt = blockIdx.x; bt < BB * TT; bt += gridDim.x) {
        int b = bt / TT;
        float acc = 0.0f;
        #pragma unroll
        for (int m = tid; m < MFEAT; m += 256)
            acc += g_qp[(size_t)bt * MFEAT + m] * g_ksum[b * MFEAT + m];
        #pragma unroll
        for (int o = 16; o; o >>= 1) acc += __shfl_xor_sync(0xFFFFFFFFu, acc, o);
        if ((tid & 31) == 0) ws[tid >> 5] = acc;
        __syncthreads();
        if (tid == 0) {
            float s = 0.0f;
            #pragma unroll
            for (int i = 0; i < 8; i++) s += ws[i];
            g_D[bt] = s;
        }
        __syncthreads();
    }

    // ---------- phase D: kptv ----------
    for (int tile = blockIdx.x; tile < KPTV_TILES; tile += gridDim.x) {
        int b = tile / ((MFEAT / 16) * (DIMV / 16));
        int rem = tile % ((MFEAT / 16) * (DIMV / 16));
        int n0 = (rem / (MFEAT / 16)) * 16;
        int m0 = (rem % (MFEAT / 16)) * 16;
        float acc = 0.0f;
        for (int t0 = 0; t0 < TT; t0 += 16) {
            int t = t0 + ty16;
            T0[ty16][tx16] = V[((size_t)b * TT + t) * DIMV + n0 + tx16] * mask[b * TT + t];
            T1[ty16][tx16] = g_kp[((size_t)b * TT + t) * MFEAT + m0 + tx16];
            __syncthreads();
            #pragma unroll
            for (int kk = 0; kk < 16; kk++)
                acc = fmaf(T0[kk][ty16], T1[kk][tx16], acc);
            __syncthreads();
        }
        g_kptv[((size_t)b * DIMV + n0 + ty16) * MFEAT + m0 + tx16] = acc;
        __syncthreads();
    }
    grid_bar();

    // ---------- phase E: y ----------
    for (int tile = blockIdx.x; tile < YF_TILES; tile += gridDim.x) {
        int b = tile / ((DIMV / 16) * (TT / 16));
        int rem = tile % ((DIMV / 16) * (TT / 16));
        int t0 = (rem / (DIMV / 16)) * 16;
        int n0 = (rem % (DIMV / 16)) * 16;
        float acc = 0.0f;
        for (int m0 = 0; m0 < MFEAT; m0 += 16) {
            T0[ty16][tx16] = g_qp[((size_t)b * TT + t0 + ty16) * MFEAT + m0 + tx16];
            T1[ty16][tx16] = g_kptv[((size_t)b * DIMV + n0 + ty16) * MFEAT + m0 + tx16];
            __syncthreads();
            #pragma unroll
            for (int kk = 0; kk < 16; kk++)
                acc = fmaf(T0[ty16][kk], T1[tx16][kk], acc);
            __syncthreads();
        }
        int t = t0 + ty16;
        float inv = 1.0f / (g_D[b * TT + t] + EPSV);
        out[((size_t)b * TT + t) * DIMV + n0 + tx16] = acc * inv * inv;
        __syncthreads();
    }

    // reset flag for the next graph replay (all blocks done with flag-dependent work)
    grid_bar();
    if (blockIdx.x == 0 && tid == 0) g_flag = 0;
}

// ---------------- launch ----------------
extern "C" void kernel_launch(void* const* d_in, const int* in_sizes, int n_in,
                              void* d_out, int out_size) {
    const float* Q    = (const float*)d_in[0];
    const float* K    = (const float*)d_in[1];
    const float* V    = (const float*)d_in[2];
    const float* mask = (const float*)d_in[3];
    const float* w    = (const float*)d_in[4];
    float* out = (float*)d_out;
    (void)in_sizes; (void)n_in; (void)out_size;

    cudaFuncSetAttribute(cert_gemm, cudaFuncAttributeMaxDynamicSharedMemorySize, CT_DYN);

    prep_all<<<64 + NROWS / 8, 256>>>(Q, K, mask, w);
    cert_gemm<<<dim3(MFEAT / 128, NROWS / 128), 256, CT_DYN>>>(out);
    fallback_kernel<<<FB_GRID, 256>>>(Q, K, V, mask, w, out);
}